// round 12
// baseline (speedup 1.0000x reference)
#include <cuda_runtime.h>

#define NBLK 144
#define NGATE 128
#define NATT 16
#define NT 1024

__device__ float g_ct[524288];    // [32 b][64 l][256 a]
__device__ float g_h[16384];      // [32][512]
__device__ float g_c[16384];
__device__ float g_cv[16384];
__device__ float g_a[2048];       // attention weights [32 b][64 l]
__device__ float g_hwp[131072];   // hW partials [16 j][32 b][256 a]
__device__ unsigned g_flag[NBLK * 8];    // top barrier (monotonic, never reset)
__device__ unsigned g_aflag[NATT * 8];   // att hwp-barrier + a-ready
__device__ unsigned g_gflag[NGATE * 8];  // gate cv-exchange barrier

struct P {
    const float *X, *ctx, *mask; const int* cmask;
    const float *W[4], *U[4], *C[4], *bs[4];
    const float *w1c, *w1h, *b1, *w2, *b2;
    float *oh, *oc, *octx;
};

typedef unsigned long long ull;

__device__ __forceinline__ float fsig(float x)  { return 1.f / (1.f + __expf(-x)); }
__device__ __forceinline__ float ftanh(float x) { return 1.f - 2.f / (1.f + __expf(2.f * x)); }
__device__ __forceinline__ float tanha(float x) { float y; asm("tanh.approx.f32 %0, %1;" : "=f"(y) : "f"(x)); return y; }
__device__ __forceinline__ ull fpack(float lo, float hi) {
    ull r; asm("mov.b64 %0, {%1, %2};" : "=l"(r) : "f"(lo), "f"(hi)); return r;
}
__device__ __forceinline__ ull fpack1(float v) {
    ull r; asm("mov.b64 %0, {%1, %1};" : "=l"(r) : "f"(v)); return r;
}
__device__ __forceinline__ void funpack(ull v, float& lo, float& hi) {
    asm("mov.b64 {%0, %1}, %2;" : "=f"(lo), "=f"(hi) : "l"(v));
}
__device__ __forceinline__ void fma2(ull& acc, ull a, ull b) {
    asm("fma.rn.f32x2 %0, %1, %2, %0;" : "+l"(acc) : "l"(a), "l"(b));
}

// Arrival: all-threads sync, then tid0 fences + stores own flag.
__device__ __forceinline__ void arrive(unsigned* slot, unsigned v) {
    __syncthreads();
    if (threadIdx.x == 0) { __threadfence(); *(volatile unsigned*)slot = v; }
}

// Wait until flags[0..CNT) (stride-8 slots) are all >= v.
template <int CNT>
__device__ __forceinline__ void waitf(unsigned* flags, unsigned v) {
    if (threadIdx.x < 32) {
        for (;;) {
            bool ok = true;
            #pragma unroll
            for (int j = 0; j < (CNT + 31) / 32; ++j) {
                int bk = threadIdx.x + j * 32;
                if (bk < CNT) ok &= (*(volatile unsigned*)&flags[bk * 8] >= v);
            }
            if (__all_sync(0xffffffffu, ok)) break;
            __nanosleep(32);
        }
        __threadfence();
    }
    __syncthreads();
}

// prologue ctx_trans; csm[512], rsm[4*260] (aliased scratch)
__device__ void ct_task(const P& p, float* csm, float* rsm, int blk, int tid) {
    const int a = tid & 255, kq = tid >> 8;
    for (int tt = blk; tt < 2048; tt += NBLK) {
        int b = tt >> 6, l = tt & 63;
        __syncthreads();
        if (tid < 512) csm[tid] = p.ctx[(b * 64 + l) * 512 + tid];
        __syncthreads();
        float acc = 0.f;
        #pragma unroll 8
        for (int i = 0; i < 128; ++i) {
            int k = kq * 128 + i;
            acc = fmaf(p.w1c[k * 256 + a], csm[k], acc);
        }
        rsm[kq * 260 + a] = acc;
        __syncthreads();
        if (tid < 256)
            g_ct[(b * 64 + l) * 256 + tid] =
                rsm[tid] + rsm[260 + tid] + rsm[520 + tid] + rsm[780 + tid] + p.b1[tid];
        __syncthreads();
    }
}

// stage 32x512 rows into vs[32][513]
__device__ __forceinline__ void gstage(float* vs, const float* src, int stride, int tid) {
    __syncthreads();
    #pragma unroll
    for (int j = 0; j < 4; ++j) {
        int i4 = tid + j * NT;
        int bb = i4 >> 7;
        int k4 = (i4 & 127) * 4;
        float4 v = __ldcg((const float4*)(src + bb * stride + k4));
        float* d = vs + bb * 513 + k4;
        d[0] = v.x; d[1] = v.y; d[2] = v.z; d[3] = v.w;
    }
    __syncthreads();
}

// 16 k per thread; acc: 8 packed f32x2 pairs
__device__ __forceinline__ void gpass(ull acc[8], const float* vs, const float* wsm,
                                      int kq, int b) {
    const float* vb = vs + b * 513;
    #pragma unroll 4
    for (int i = 0; i < 16; ++i) {
        int k = i * 32 + kq;
        ull vv = fpack1(vb[k]);
        #pragma unroll
        for (int g = 0; g < 4; ++g) {
            ulonglong2 w = *(const ulonglong2*)(wsm + (g * 512 + k) * 4);
            fma2(acc[g * 2],     w.x, vv);
            fma2(acc[g * 2 + 1], w.y, vv);
        }
    }
}

__device__ void gate_role(const P& p, char* smem, int blk, int tid, unsigned B) {
    float* wsm  = (float*)smem;        // 24576 f [mat][g][k][4]
    float* vs   = wsm + 24576;         // 16416 f [32][513]
    float* red  = vs;                  // alias
    float* csm  = vs;                  // prologue alias
    float* rsm  = vs + 512;
    float* asm_ = vs + 16416;          // 2048 f [32 b][64 l]
    float* red2 = asm_ + 2048;         // 1152 f [(b*4+j)][9]
    const int hc = blk, b = tid & 31, kq = tid >> 5;

    for (int i = tid; i < 24576; i += NT) {
        int j = i & 3, k = (i >> 2) & 511, g = (i >> 11) & 3, m = i >> 13;
        const float* s = (m == 0) ? p.W[g] : (m == 1) ? p.U[g] : p.C[g];
        wsm[i] = s[k * 512 + hc * 4 + j];
    }
    { int zi = blk * NT + tid; if (zi < 16384) { g_h[zi] = 0.f; g_c[zi] = 0.f; } }
    ct_task(p, csm, rsm, blk, tid);

    ull b0[8];
    #pragma unroll
    for (int g = 0; g < 4; ++g) {
        float4 bf = *(const float4*)(p.bs[g] + hc * 4);
        b0[g * 2]     = fpack(bf.x, bf.y);
        b0[g * 2 + 1] = fpack(bf.z, bf.w);
    }
    const ull zz = fpack(0.f, 0.f);

    arrive(&g_flag[blk * 8], B + 1);
    // overlap: X(0) stage + x@W into acc before first wait
    ull acc[8];
    gstage(vs, p.X, 65536, tid);
    #pragma unroll
    for (int q = 0; q < 8; ++q) acc[q] = (kq == 0) ? b0[q] : zz;
    gpass(acc, vs, wsm, kq, b);

    for (int t = 0; t < 128; ++t) {
        const unsigned V = B + 4u * (unsigned)t;
        waitf<NBLK>(g_flag, V + 1);               // h(t-1), c sealed; a/cv consumed
        gstage(vs, g_h, 512, tid);
        gpass(acc, vs, wsm + 8192, kq, b);        // h @ U
        waitf<NATT>(g_aflag, V + 3);              // a(t) published
        asm_[tid]      = __ldcg(&g_a[tid]);
        asm_[NT + tid] = __ldcg(&g_a[NT + tid]);
        __syncthreads();
        // own cv slice: d = hc*4 + j, all 32 b
        {
            int bb = tid >> 5, j = (tid >> 3) & 3, lr = tid & 7;
            float s = 0.f;
            const float* cp = p.ctx + (bb * 64) * 512 + hc * 4 + j;
            #pragma unroll
            for (int i = 0; i < 8; ++i) {
                int l = lr + i * 8;
                s = fmaf(asm_[bb * 64 + l], __ldg(cp + l * 512), s);
            }
            red2[(bb * 4 + j) * 9 + lr] = s;
        }
        __syncthreads();
        if (tid < 128) {
            int bb = tid >> 2, j = tid & 3;
            const float* r = red2 + tid * 9;
            float cvv = ((r[0] + r[1]) + (r[2] + r[3])) + ((r[4] + r[5]) + (r[6] + r[7]));
            g_cv[bb * 512 + hc * 4 + j] = cvv;
            p.octx[(bb * 128 + t) * 512 + hc * 4 + j] = cvv;
        }
        arrive(&g_gflag[blk * 8], V + 4);
        waitf<NGATE>(g_gflag, V + 4);             // full cv assembled
        gstage(vs, g_cv, 512, tid);
        gpass(acc, vs, wsm + 16384, kq, b);       // cv @ C
        __syncthreads();
        float av4[4][4];
        #pragma unroll
        for (int g = 0; g < 4; ++g) {
            funpack(acc[g * 2],     av4[g][0], av4[g][1]);
            funpack(acc[g * 2 + 1], av4[g][2], av4[g][3]);
        }
        if (kq >= 16) {
            int q = kq - 16;
            #pragma unroll
            for (int g = 0; g < 4; ++g)
                #pragma unroll
                for (int j = 0; j < 4; ++j)
                    red[((g * 4 + j) * 16 + q) * 33 + b] = av4[g][j];
        }
        __syncthreads();
        if (kq < 16) {
            #pragma unroll
            for (int g = 0; g < 4; ++g)
                #pragma unroll
                for (int j = 0; j < 4; ++j)
                    red[((g * 4 + j) * 16 + kq) * 33 + b] += av4[g][j];
        }
        __syncthreads();
        if (tid < 128) {
            int bb = tid >> 2, j = tid & 3, h = hc * 4 + j;
            float pre[4];
            #pragma unroll
            for (int g = 0; g < 4; ++g) {
                int o = g * 4 + j;
                float s = 0.f;
                #pragma unroll
                for (int q = 0; q < 16; ++q) s += red[(o * 16 + q) * 33 + bb];
                pre[g] = s;
            }
            float iv = fsig(pre[0]), fv = fsig(pre[1]);
            float gv = ftanh(pre[2]), ov = fsig(pre[3]);
            float co = __ldcg(&g_c[bb * 512 + h]), ho = __ldcg(&g_h[bb * 512 + h]);
            float cn = fv * co + iv * gv;
            float hn = ov * ftanh(cn);
            float m = p.mask[bb * 128 + t];
            hn = (1.f - m) * ho + m * hn;
            cn = (1.f - m) * co + m * cn;
            g_h[bb * 512 + h] = hn;
            g_c[bb * 512 + h] = cn;
            p.oh[(bb * 128 + t) * 512 + h] = hn;
            p.oc[(bb * 128 + t) * 512 + h] = cn;
        }
        arrive(&g_flag[blk * 8], V + 5);
        if (t < 127) {                             // overlap X(t+1) + x@W
            gstage(vs, p.X + (t + 1) * 512, 65536, tid);
            #pragma unroll
            for (int q = 0; q < 8; ++q) acc[q] = (kq == 0) ? b0[q] : zz;
            gpass(acc, vs, wsm, kq, b);
        }
    }
}

__device__ void att_role(const P& p, char* smem, int blk, int tid, unsigned B) {
    float* ctsm = (float*)smem;        // 32768 f [2 b][64 l][256 a]
    float* wk   = ctsm + 32768;        // 8192 f: w1h rows [32 k][256 a]
    float* hk   = wk + 8192;           // 1056 f [32 b][33]
    float* hwsm = hk + 1056;           // 512 f [2][256]
    float* w2sm = hwsm + 512;          // 256
    float* esm  = w2sm + 256;          // 128
    float* ssum = esm + 128;           // 16
    float* csm  = ctsm; float* rsm = ctsm + 512;
    const int jslot = blk - NGATE, b0 = jslot * 2;
    const int a2 = tid & 127, bq = tid >> 7;
    const int ww = tid >> 5, lane = tid & 31;

    ct_task(p, csm, rsm, blk, tid);
    for (int i = tid; i < 8192; i += NT) wk[i] = p.w1h[jslot * 8192 + i];
    arrive(&g_flag[blk * 8], B + 1);
    waitf<NBLK>(g_flag, B + 1);
    for (int i = tid; i < 32768; i += NT) ctsm[i] = __ldcg(&g_ct[b0 * 16384 + i]);
    if (tid < 256) w2sm[tid] = p.w2[tid];
    const float b2v = p.b2[0];
    const ull zz = fpack(0.f, 0.f);
    __syncthreads();

    for (int t = 0; t < 128; ++t) {
        const unsigned V = B + 4u * (unsigned)t;
        waitf<NBLK>(g_flag, V + 1);               // h(t-1) sealed
        { int bb = tid >> 5, kk = tid & 31;
          hk[bb * 33 + kk] = __ldcg(&g_h[bb * 512 + jslot * 32 + kk]); }
        __syncthreads();
        // partial hW over own 32-k slice, all 32 b
        ull acc[4];
        #pragma unroll
        for (int i = 0; i < 4; ++i) acc[i] = zz;
        #pragma unroll 8
        for (int k = 0; k < 32; ++k) {
            ull w = *(const ull*)&wk[k * 256 + a2 * 2];
            #pragma unroll
            for (int i = 0; i < 4; ++i)
                fma2(acc[i], w, fpack1(hk[(bq + i * 8) * 33 + k]));
        }
        #pragma unroll
        for (int i = 0; i < 4; ++i)
            *(ull*)&g_hwp[jslot * 8192 + (bq + i * 8) * 256 + a2 * 2] = acc[i];
        arrive(&g_aflag[jslot * 8], V + 2);
        waitf<NATT>(g_aflag, V + 2);              // all partials in
        if (tid < 512) {
            int bb = tid >> 8, aa = tid & 255;
            float s = 0.f;
            #pragma unroll
            for (int jj = 0; jj < 16; ++jj)
                s += __ldcg(&g_hwp[jj * 8192 + (b0 + bb) * 256 + aa]);
            hwsm[bb * 256 + aa] = s;
        }
        __syncthreads();
        {
            int bb = ww >> 4;
            #pragma unroll
            for (int lq = 0; lq < 4; ++lq) {
                int l = (ww & 15) * 4 + lq;
                float s = 0.f;
                #pragma unroll
                for (int j = 0; j < 8; ++j) {
                    int aa = j * 32 + lane;
                    float x = ctsm[(bb * 64 + l) * 256 + aa] + hwsm[bb * 256 + aa];
                    s = fmaf(tanha(x), w2sm[aa], s);
                }
                #pragma unroll
                for (int o = 16; o; o >>= 1) s += __shfl_xor_sync(0xffffffffu, s, o);
                if (lane == 0)
                    esm[bb * 64 + l] = __expf(s + b2v) * (float)__ldg(&p.cmask[(b0 + bb) * 64 + l]);
            }
        }
        __syncthreads();
        if (tid < 2) {
            float s = 0.f;
            for (int l = 0; l < 64; ++l) s += esm[tid * 64 + l];
            ssum[tid] = s;
        }
        __syncthreads();
        if (tid < 128)
            g_a[b0 * 64 + tid] = esm[tid] / ssum[tid >> 6];
        arrive(&g_aflag[jslot * 8], V + 3);       // a(t) published
        arrive(&g_flag[blk * 8], V + 5);          // top arrival for t+1
    }
}

extern "C" __global__ void __launch_bounds__(NT, 1) cond_lstm(P p) {
    extern __shared__ char smem[];
    const unsigned B = *(volatile unsigned*)&g_flag[blockIdx.x * 8];
    if (blockIdx.x < NGATE) gate_role(p, smem, blockIdx.x, threadIdx.x, B);
    else                    att_role(p, smem, blockIdx.x, threadIdx.x, B);
}

#define SMEM_BYTES 176768

extern "C" void kernel_launch(void* const* d_in, const int* in_sizes, int n_in,
                              void* d_out, int out_size) {
    (void)in_sizes; (void)n_in; (void)out_size;
    P p;
    p.X     = (const float*)d_in[0];
    p.ctx   = (const float*)d_in[1];
    p.mask  = (const float*)d_in[2];
    p.cmask = (const int*)d_in[3];
    for (int g = 0; g < 4; ++g) {
        p.W[g]  = (const float*)d_in[4 + 4 * g];
        p.U[g]  = (const float*)d_in[5 + 4 * g];
        p.C[g]  = (const float*)d_in[6 + 4 * g];
        p.bs[g] = (const float*)d_in[7 + 4 * g];
    }
    p.w1c = (const float*)d_in[20];
    p.w1h = (const float*)d_in[21];
    p.b1  = (const float*)d_in[22];
    p.w2  = (const float*)d_in[23];
    p.b2  = (const float*)d_in[24];
    float* out = (float*)d_out;
    p.oh   = out;
    p.oc   = out + 32 * 128 * 512;
    p.octx = out + 2 * 32 * 128 * 512;

    cudaFuncSetAttribute(cond_lstm, cudaFuncAttributeMaxDynamicSharedMemorySize, SMEM_BYTES);
    cond_lstm<<<NBLK, NT, SMEM_BYTES>>>(p);
}

// round 15
// speedup vs baseline: 1.3272x; 1.3272x over previous
#include <cuda_runtime.h>

#define NBLK 144
#define NGATE 128
#define NATT 16
#define NT 1024

__device__ float g_xw[8388608];   // [128 t][128 hc][32 b][16 o] = x@W + bias
__device__ float g_h[16384];      // [32][512]
__device__ float g_c[16384];
__device__ float g_cv[16384];
__device__ unsigned g_flag[NBLK * 8];   // monotonic (never reset)

struct P {
    const float *X, *ctx, *mask; const int* cmask;
    const float *W[4], *U[4], *C[4], *bs[4];
    const float *w1c, *w1h, *b1, *w2, *b2;
    float *oh, *oc, *octx;
};

typedef unsigned long long ull;

__device__ __forceinline__ float fsig(float x)  { return 1.f / (1.f + __expf(-x)); }
__device__ __forceinline__ float ftanh(float x) { return 1.f - 2.f / (1.f + __expf(2.f * x)); }
__device__ __forceinline__ float tanha(float x) { float y; asm("tanh.approx.f32 %0, %1;" : "=f"(y) : "f"(x)); return y; }
__device__ __forceinline__ ull fpack(float lo, float hi) {
    ull r; asm("mov.b64 %0, {%1, %2};" : "=l"(r) : "f"(lo), "f"(hi)); return r;
}
__device__ __forceinline__ ull fpack1(float v) {
    ull r; asm("mov.b64 %0, {%1, %1};" : "=l"(r) : "f"(v)); return r;
}
__device__ __forceinline__ void funpack(ull v, float& lo, float& hi) {
    asm("mov.b64 {%0, %1}, %2;" : "=f"(lo), "=f"(hi) : "l"(v));
}
__device__ __forceinline__ void fma2(ull& acc, ull a, ull b) {
    asm("fma.rn.f32x2 %0, %1, %2, %0;" : "+l"(acc) : "l"(a), "l"(b));
}

// Full grid barrier, monotonic value fv (R9-proven; flags never reset, base
// re-read each launch so graph replays see identical behavior).
__device__ __forceinline__ void gridbar(unsigned fv) {
    __syncthreads();
    if (threadIdx.x < 32) {
        if (threadIdx.x == 0) {
            __threadfence();
            *(volatile unsigned*)&g_flag[blockIdx.x * 8] = fv;
        }
        for (;;) {
            bool ok = true;
            #pragma unroll
            for (int j = 0; j < 5; ++j) {
                int bk = threadIdx.x + j * 32;
                if (bk < NBLK) ok &= (*(volatile unsigned*)&g_flag[bk * 8] >= fv);
            }
            if (__all_sync(0xffffffffu, ok)) break;
            __nanosleep(32);
        }
        __threadfence();
    }
    __syncthreads();
}

// stage 32x512 rows into vs[32][513]
__device__ __forceinline__ void gstage(float* vs, const float* src, int stride, int tid) {
    __syncthreads();
    #pragma unroll
    for (int j = 0; j < 4; ++j) {
        int i4 = tid + j * NT;
        int bb = i4 >> 7;
        int k4 = (i4 & 127) * 4;
        float4 v = __ldcg((const float4*)(src + bb * stride + k4));
        float* d = vs + bb * 513 + k4;
        d[0] = v.x; d[1] = v.y; d[2] = v.z; d[3] = v.w;
    }
    __syncthreads();
}

// 16 k per thread; acc: 8 packed f32x2 pairs
__device__ __forceinline__ void gpass(ull acc[8], const float* vs, const float* wsm,
                                      int kq, int b) {
    const float* vb = vs + b * 513;
    #pragma unroll 8
    for (int i = 0; i < 16; ++i) {
        int k = i * 32 + kq;
        ull vv = fpack1(vb[k]);
        #pragma unroll
        for (int g = 0; g < 4; ++g) {
            ulonglong2 w = *(const ulonglong2*)(wsm + (g * 512 + k) * 4);
            fma2(acc[g * 2],     w.x, vv);
            fma2(acc[g * 2 + 1], w.y, vv);
        }
    }
}

__device__ void gate_role(const P& p, char* smem, int blk, int tid, unsigned B) {
    float* wsm = (float*)smem;        // 24576 f [mat][g][k][4]  (W,U,C)
    float* vs  = wsm + 24576;         // 16416 f [32][513]
    float* red = vs;                  // alias (<=8447 f)
    const int hc = blk, b = tid & 31, kq = tid >> 5;   // kq 0..31
    const int jj = tid & 3;

    for (int i = tid; i < 24576; i += NT) {
        int j = i & 3, k = (i >> 2) & 511, g = (i >> 11) & 3, m = i >> 13;
        const float* s = (m == 0) ? p.W[g] : (m == 1) ? p.U[g] : p.C[g];
        wsm[i] = s[k * 512 + hc * 4 + j];
    }
    { int zi = blk * NT + tid; if (zi < 16384) { g_h[zi] = 0.f; g_c[zi] = 0.f; } }
    __syncthreads();

    // bias for this thread's output (tid<128 epilogue role)
    float bj[4];
    if (tid < 128) {
        #pragma unroll
        for (int g = 0; g < 4; ++g) bj[g] = p.bs[g][hc * 4 + jj];
    }
    const ull zz = fpack(0.f, 0.f);

    // ---- prologue: xw[t] = x_t @ W + bias for all t (no barriers: free-running) ----
    for (int t = 0; t < 128; ++t) {
        gstage(vs, p.X + t * 512, 65536, tid);
        ull acc[8];
        #pragma unroll
        for (int q = 0; q < 8; ++q) acc[q] = zz;
        gpass(acc, vs, wsm, kq, b);
        __syncthreads();
        float av4[4][4];
        #pragma unroll
        for (int g = 0; g < 4; ++g) {
            funpack(acc[g * 2],     av4[g][0], av4[g][1]);
            funpack(acc[g * 2 + 1], av4[g][2], av4[g][3]);
        }
        if (kq >= 16) {
            int q = kq - 16;
            #pragma unroll
            for (int g = 0; g < 4; ++g)
                #pragma unroll
                for (int j = 0; j < 4; ++j)
                    red[((g * 4 + j) * 16 + q) * 33 + b] = av4[g][j];
        }
        __syncthreads();
        if (kq < 16) {
            #pragma unroll
            for (int g = 0; g < 4; ++g)
                #pragma unroll
                for (int j = 0; j < 4; ++j)
                    red[((g * 4 + j) * 16 + kq) * 33 + b] += av4[g][j];
        }
        __syncthreads();
        if (tid < 128) {
            int bb = tid >> 2;
            #pragma unroll
            for (int g = 0; g < 4; ++g) {
                int o = g * 4 + jj;
                float s = 0.f;
                #pragma unroll
                for (int q = 0; q < 16; ++q) s += red[(o * 16 + q) * 33 + bb];
                g_xw[t * 65536 + hc * 512 + bb * 16 + o] = s + bj[g];
            }
        }
    }
    gridbar(B + 1);

    unsigned bar = B + 2;
    for (int t = 0; t < 128; ++t) {
        // xw(t) acc-init BEFORE barrier: hides LDG behind the wait
        ull acc[8];
        if (kq == 0) {
            const float4* xp = (const float4*)(g_xw + t * 65536 + hc * 512 + b * 16);
            float4 x0 = __ldcg(xp + 0), x1 = __ldcg(xp + 1);
            float4 x2 = __ldcg(xp + 2), x3 = __ldcg(xp + 3);
            acc[0] = fpack(x0.x, x0.y); acc[1] = fpack(x0.z, x0.w);
            acc[2] = fpack(x1.x, x1.y); acc[3] = fpack(x1.z, x1.w);
            acc[4] = fpack(x2.x, x2.y); acc[5] = fpack(x2.z, x2.w);
            acc[6] = fpack(x3.x, x3.y); acc[7] = fpack(x3.z, x3.w);
        } else {
            #pragma unroll
            for (int q = 0; q < 8; ++q) acc[q] = zz;
        }
        gridbar(bar); bar++;                      // h,c,cv of t-1 sealed
        gstage(vs, g_h, 512, tid);
        gpass(acc, vs, wsm + 8192, kq, b);        // h @ U
        gridbar(bar); bar++;                      // cv ready
        gstage(vs, g_cv, 512, tid);
        gpass(acc, vs, wsm + 16384, kq, b);       // cv @ C
        __syncthreads();
        float av4[4][4];
        #pragma unroll
        for (int g = 0; g < 4; ++g) {
            funpack(acc[g * 2],     av4[g][0], av4[g][1]);
            funpack(acc[g * 2 + 1], av4[g][2], av4[g][3]);
        }
        if (kq >= 16) {
            int q = kq - 16;
            #pragma unroll
            for (int g = 0; g < 4; ++g)
                #pragma unroll
                for (int j = 0; j < 4; ++j)
                    red[((g * 4 + j) * 16 + q) * 33 + b] = av4[g][j];
        }
        __syncthreads();
        if (kq < 16) {
            #pragma unroll
            for (int g = 0; g < 4; ++g)
                #pragma unroll
                for (int j = 0; j < 4; ++j)
                    red[((g * 4 + j) * 16 + kq) * 33 + b] += av4[g][j];
        }
        __syncthreads();
        if (tid < 128) {
            int bb = tid >> 2, h = hc * 4 + jj;
            float pre[4];
            #pragma unroll
            for (int g = 0; g < 4; ++g) {
                int o = g * 4 + jj;
                float s = 0.f;
                #pragma unroll
                for (int q = 0; q < 16; ++q) s += red[(o * 16 + q) * 33 + bb];
                pre[g] = s;
            }
            float iv = fsig(pre[0]), fv = fsig(pre[1]);
            float gv = ftanh(pre[2]), ov = fsig(pre[3]);
            float co = __ldcg(&g_c[bb * 512 + h]), ho = __ldcg(&g_h[bb * 512 + h]);
            float cn = fv * co + iv * gv;
            float hn = ov * ftanh(cn);
            float m = p.mask[bb * 128 + t];
            hn = (1.f - m) * ho + m * hn;
            cn = (1.f - m) * co + m * cn;
            g_h[bb * 512 + h] = hn;
            g_c[bb * 512 + h] = cn;
            p.oh[(bb * 128 + t) * 512 + h] = hn;
            p.oc[(bb * 128 + t) * 512 + h] = cn;
        }
    }
}

__device__ void att_role(const P& p, char* smem, int blk, int tid, unsigned B) {
    float* ctsm = (float*)smem;       // 32768 f [2][64][256]
    float* csm  = ctsm + 32768;       // 512 (prologue ctx row)
    float* rsm  = csm + 512;          // 1040 (prologue reduce)
    float* hsm  = rsm + 1040;         // 1024
    float* redh = hsm + 1024;         // 4128: [2][8][258]
    float* hwsm = redh + 4128;        // 512: [2][256]
    float* w2sm = hwsm + 512;         // 256
    float* esm  = w2sm + 256;         // 128
    float* av   = esm + 128;          // 128
    float* ssum = av + 128;           // 16
    const int b0 = (blk - NGATE) * 2;
    const int a2 = tid & 127, kq = tid >> 7;   // kq 0..7
    const int ww = tid >> 5, lane = tid & 31;

    // ---- prologue: ct tile for OWN two batches, straight into smem ----
    {
        const int a = tid & 255, kq4 = tid >> 8;   // kq4 0..3
        for (int tt = 0; tt < 128; ++tt) {
            int bb = tt >> 6, l = tt & 63;
            __syncthreads();
            if (tid < 512) csm[tid] = p.ctx[((b0 + bb) * 64 + l) * 512 + tid];
            __syncthreads();
            float acc = 0.f;
            #pragma unroll 8
            for (int i = 0; i < 128; ++i) {
                int k = kq4 * 128 + i;
                acc = fmaf(p.w1c[k * 256 + a], csm[k], acc);
            }
            rsm[kq4 * 260 + a] = acc;
            __syncthreads();
            if (tid < 256)
                ctsm[(bb * 64 + l) * 256 + tid] =
                    rsm[tid] + rsm[260 + tid] + rsm[520 + tid] + rsm[780 + tid] + p.b1[tid];
        }
        __syncthreads();
    }
    if (tid < 256) w2sm[tid] = p.w2[tid];
    const float b2v = p.b2[0];
    const ull zz = fpack(0.f, 0.f);
    gridbar(B + 1);

    unsigned bar = B + 2;
    for (int t = 0; t < 128; ++t) {
        gridbar(bar); bar++;                      // h(t-1) sealed
        hsm[tid] = __ldcg(&g_h[b0 * 512 + tid]);
        __syncthreads();
        // hW: thread (a2, kq): f32x2 over a-pair a2, k = i*8+kq
        ull ac0 = zz, ac1 = zz;
        #pragma unroll 8
        for (int i = 0; i < 64; ++i) {
            int k = i * 8 + kq;
            ull w = __ldg((const ull*)(p.w1h + k * 256 + a2 * 2));
            fma2(ac0, w, fpack1(hsm[k]));
            fma2(ac1, w, fpack1(hsm[512 + k]));
        }
        {
            float x, y;
            funpack(ac0, x, y);
            redh[kq * 258 + a2 * 2] = x;  redh[kq * 258 + a2 * 2 + 1] = y;
            funpack(ac1, x, y);
            redh[2064 + kq * 258 + a2 * 2] = x;  redh[2064 + kq * 258 + a2 * 2 + 1] = y;
        }
        __syncthreads();
        if (tid < 512) {
            int bb = tid >> 8, aa = tid & 255;
            float s = 0.f;
            #pragma unroll
            for (int q = 0; q < 8; ++q) s += redh[bb * 2064 + q * 258 + aa];
            hwsm[bb * 256 + aa] = s;
        }
        __syncthreads();
        // scores: warp ww -> bb = ww>>4, l = (ww&15)*4 + lq ; tanh.approx
        {
            int bb = ww >> 4;
            #pragma unroll
            for (int lq = 0; lq < 4; ++lq) {
                int l = (ww & 15) * 4 + lq;
                float s = 0.f;
                #pragma unroll
                for (int j = 0; j < 8; ++j) {
                    int aa = j * 32 + lane;
                    float x = ctsm[(bb * 64 + l) * 256 + aa] + hwsm[bb * 256 + aa];
                    s = fmaf(tanha(x), w2sm[aa], s);
                }
                #pragma unroll
                for (int o = 16; o; o >>= 1) s += __shfl_xor_sync(0xffffffffu, s, o);
                if (lane == 0)
                    esm[bb * 64 + l] = __expf(s + b2v) * (float)__ldg(&p.cmask[(b0 + bb) * 64 + l]);
            }
        }
        __syncthreads();
        if (tid < 2) {
            float s = 0.f;
            for (int l = 0; l < 64; ++l) s += esm[tid * 64 + l];
            ssum[tid] = s;
        }
        __syncthreads();
        if (tid < 128) av[tid] = esm[tid] / ssum[tid >> 6];
        __syncthreads();
        // ctx_vec: thread owns (bb = tid>>9, d = tid&511)
        {
            int bb = tid >> 9, d = tid & 511;
            float c = 0.f;
            const float* cp = p.ctx + ((b0 + bb) * 64) * 512 + d;
            const float* ap = av + bb * 64;
            #pragma unroll 8
            for (int l = 0; l < 64; ++l)
                c = fmaf(ap[l], __ldg(cp + l * 512), c);
            g_cv[(b0 + bb) * 512 + d] = c;
            p.octx[((b0 + bb) * 128 + t) * 512 + d] = c;
        }
        gridbar(bar); bar++;                      // cv published
    }
}

extern "C" __global__ void __launch_bounds__(NT, 1) cond_lstm(P p) {
    extern __shared__ char smem[];
    const unsigned B = *(volatile unsigned*)&g_flag[blockIdx.x * 8];
    if (blockIdx.x < NGATE) gate_role(p, smem, blockIdx.x, threadIdx.x, B);
    else                    att_role(p, smem, blockIdx.x, threadIdx.x, B);
}

#define SMEM_BYTES 163968

extern "C" void kernel_launch(void* const* d_in, const int* in_sizes, int n_in,
                              void* d_out, int out_size) {
    (void)in_sizes; (void)n_in; (void)out_size;
    P p;
    p.X     = (const float*)d_in[0];
    p.ctx   = (const float*)d_in[1];
    p.mask  = (const float*)d_in[2];
    p.cmask = (const int*)d_in[3];
    for (int g = 0; g < 4; ++g) {
        p.W[g]  = (const float*)d_in[4 + 4 * g];
        p.U[g]  = (const float*)d_in[5 + 4 * g];
        p.C[g]  = (const float*)d_in[6 + 4 * g];
        p.bs[g] = (const float*)d_in[7 + 4 * g];
    }
    p.w1c = (const float*)d_in[20];
    p.w1h = (const float*)d_in[21];
    p.b1  = (const float*)d_in[22];
    p.w2  = (const float*)d_in[23];
    p.b2  = (const float*)d_in[24];
    float* out = (float*)d_out;
    p.oh   = out;
    p.oc   = out + 32 * 128 * 512;
    p.octx = out + 2 * 32 * 128 * 512;

    cudaFuncSetAttribute(cond_lstm, cudaFuncAttributeMaxDynamicSharedMemorySize, SMEM_BYTES);
    cond_lstm<<<NBLK, NT, SMEM_BYTES>>>(p);
}